// round 3
// baseline (speedup 1.0000x reference)
#include <cuda_runtime.h>
#include <cuda_fp16.h>
#include <cstdint>

#define N_DIM 512

// ---------------- scratch (no allocs allowed) ----------------
__device__ __half g_Bh[128 * 512];                 // fp16 W, rows 0..63 = Ws, 64..127 = Wo
__device__ float  g_P[(size_t)100000 * 128];       // P[node][0..63]=s-scores, [64..127]=o-scores

// ---------------- helpers ----------------
__device__ __forceinline__ uint32_t smem_u32(const void* p) {
    uint32_t a;
    asm("{ .reg .u64 t; cvta.to.shared.u64 t, %1; cvt.u32.u64 %0, t; }" : "=r"(a) : "l"(p));
    return a;
}
__device__ __forceinline__ void ldsm4(uint32_t r[4], uint32_t a) {
    asm volatile("ldmatrix.sync.aligned.m8n8.x4.shared.b16 {%0,%1,%2,%3}, [%4];"
                 : "=r"(r[0]), "=r"(r[1]), "=r"(r[2]), "=r"(r[3]) : "r"(a));
}
__device__ __forceinline__ void hmma16816(float d[4], const uint32_t a[4], uint32_t b0, uint32_t b1) {
    asm volatile("mma.sync.aligned.m16n8k16.row.col.f32.f16.f16.f32 "
                 "{%0,%1,%2,%3},{%4,%5,%6,%7},{%8,%9},{%0,%1,%2,%3};"
                 : "+f"(d[0]), "+f"(d[1]), "+f"(d[2]), "+f"(d[3])
                 : "r"(a[0]), "r"(a[1]), "r"(a[2]), "r"(a[3]), "r"(b0), "r"(b1));
}

// smem: A_hi[2][128][72] + A_lo[2][128][72] + B[2][128][72] halfs (pad 72 -> conflict-free)
#define LROW 72
#define BUF_HALFS (128 * LROW)
#define SMEM_BYTES (6 * BUF_HALFS * 2)   // 110592

// ---------------- kernel 0: W fp32 -> fp16, reorder to [128][512] ----------------
__global__ void prep_kernel(const float* __restrict__ W) {
    int idx = blockIdx.x * blockDim.x + threadIdx.x;
    if (idx >= 128 * 512) return;
    int n = idx >> 9, k = idx & 511;
    float x = (n < 64) ? W[n * 1024 + k] : W[(n - 64) * 1024 + 512 + k];
    g_Bh[idx] = __float2half_rn(x);
}

// ---------------- kernel 1: P = emb @ B^T via mma.sync (A fp16 hi/lo split) ----------------
__global__ __launch_bounds__(256) void gemm_kernel(const float* __restrict__ emb, int n_nodes) {
    extern __shared__ __half sm[];
    const int tid = threadIdx.x;
    const int lane = tid & 31;
    const int wid = tid >> 5;
    const int ctaM = blockIdx.x * 128;

    __half* AH = sm;
    __half* AL = sm + 2 * BUF_HALFS;
    __half* BS = sm + 4 * BUF_HALFS;
    const uint32_t sbase = smem_u32(sm);
    const uint32_t AHb = sbase;
    const uint32_t ALb = sbase + 2 * BUF_HALFS * 2;
    const uint32_t BSb = sbase + 4 * BUF_HALFS * 2;

    // producer mapping: 2 threads per row, each handles 32 columns of the 64-col chunk
    const int prow = tid >> 1;
    const int pcol = (tid & 1) * 32;
    int arow = ctaM + prow;
    if (arow >= n_nodes) arow = n_nodes - 1;
    const float4* ag = (const float4*)(emb + (size_t)arow * N_DIM);
    const uint4*  bg = (const uint4*)(g_Bh + prow * N_DIM);

    uint2 hiA[8], loA[8];
    uint4 stB[4];

    auto LOAD = [&](int c) {
        int fbase = c * 16 + (pcol >> 2);
        #pragma unroll
        for (int i = 0; i < 8; i++) {
            float4 v = ag[fbase + i];
            __half2 h0 = __floats2half2_rn(v.x, v.y);
            __half2 h1 = __floats2half2_rn(v.z, v.w);
            float2 f0 = __half22float2(h0), f1 = __half22float2(h1);
            __half2 l0 = __floats2half2_rn(v.x - f0.x, v.y - f0.y);
            __half2 l1 = __floats2half2_rn(v.z - f1.x, v.w - f1.y);
            hiA[i].x = *(uint32_t*)&h0; hiA[i].y = *(uint32_t*)&h1;
            loA[i].x = *(uint32_t*)&l0; loA[i].y = *(uint32_t*)&l1;
        }
        int ubase = c * 8 + (pcol >> 3);
        #pragma unroll
        for (int i = 0; i < 4; i++) stB[i] = bg[ubase + i];
    };
    auto STORE = [&](int buf) {
        int o = buf * BUF_HALFS + prow * LROW + pcol;
        #pragma unroll
        for (int i = 0; i < 8; i++) {
            *(uint2*)&AH[o + 4 * i] = hiA[i];
            *(uint2*)&AL[o + 4 * i] = loA[i];
        }
        #pragma unroll
        for (int i = 0; i < 4; i++) *(uint4*)&BS[o + 8 * i] = stB[i];
    };

    float acc[4][4][4];
    #pragma unroll
    for (int i = 0; i < 4; i++)
        #pragma unroll
        for (int j = 0; j < 4; j++)
            #pragma unroll
            for (int k = 0; k < 4; k++) acc[i][j][k] = 0.0f;

    const int wm = wid & 1;   // M-tile of 64
    const int wn = wid >> 1;  // N-tile of 32

    LOAD(0);
    STORE(0);
    __syncthreads();

    for (int c = 0; c < 8; c++) {
        const int buf = c & 1;
        if (c < 7) LOAD(c + 1);   // LDGs in flight during mma below

        const uint32_t ah_r = AHb + buf * (BUF_HALFS * 2);
        const uint32_t al_r = ALb + buf * (BUF_HALFS * 2);
        const uint32_t bs_r = BSb + buf * (BUF_HALFS * 2);

        #pragma unroll
        for (int ks = 0; ks < 4; ks++) {
            uint32_t afr[4][4], alr[4][4], bfr[2][4];
            const int acol = ks * 16 + (lane >> 4) * 8;
            #pragma unroll
            for (int mt = 0; mt < 4; mt++) {
                const int ar = wm * 64 + mt * 16 + (lane & 15);
                const uint32_t off = (uint32_t)(ar * LROW + acol) * 2;
                ldsm4(afr[mt], ah_r + off);
                ldsm4(alr[mt], al_r + off);
            }
            const int bk = ks * 16 + ((lane >> 3) & 1) * 8;
            #pragma unroll
            for (int nt = 0; nt < 2; nt++) {
                const int br = wn * 32 + nt * 16 + (lane & 7) + ((lane >> 4) & 1) * 8;
                ldsm4(bfr[nt], bs_r + (uint32_t)(br * LROW + bk) * 2);
            }
            #pragma unroll
            for (int mt = 0; mt < 4; mt++)
                #pragma unroll
                for (int nf = 0; nf < 4; nf++) {
                    const uint32_t b0 = bfr[nf >> 1][(nf & 1) * 2];
                    const uint32_t b1 = bfr[nf >> 1][(nf & 1) * 2 + 1];
                    hmma16816(acc[mt][nf], afr[mt], b0, b1);
                    hmma16816(acc[mt][nf], alr[mt], b0, b1);
                }
        }
        if (c < 7) {
            __syncthreads();
            STORE((c + 1) & 1);
            __syncthreads();
        }
    }

    // epilogue: write P
    #pragma unroll
    for (int mt = 0; mt < 4; mt++) {
        const int r0 = ctaM + wm * 64 + mt * 16 + (lane >> 2);
        const int r1 = r0 + 8;
        #pragma unroll
        for (int nf = 0; nf < 4; nf++) {
            const int col = wn * 32 + nf * 8 + (lane & 3) * 2;
            if (r0 < n_nodes)
                *(float2*)&g_P[(size_t)r0 * 128 + col] = make_float2(acc[mt][nf][0], acc[mt][nf][1]);
            if (r1 < n_nodes)
                *(float2*)&g_P[(size_t)r1 * 128 + col] = make_float2(acc[mt][nf][2], acc[mt][nf][3]);
        }
    }
}

// ---------------- kernel 2: per-triple gather-combine ----------------
__global__ __launch_bounds__(256) void gather_kernel(const int* __restrict__ triples,
                                                     const float* __restrict__ b,
                                                     float* __restrict__ out, int n) {
    int t = blockIdx.x * blockDim.x + threadIdx.x;
    if (t >= n) return;
    int s = triples[t];
    int r = triples[n + t];
    int o = triples[2 * n + t];
    out[t] = __ldg(&g_P[(size_t)s * 128 + r]) + __ldg(&g_P[(size_t)o * 128 + 64 + r]) + __ldg(&b[r]);
}

extern "C" void kernel_launch(void* const* d_in, const int* in_sizes, int n_in,
                              void* d_out, int out_size)
{
    const float* emb     = (const float*)d_in[0];
    const float* W       = (const float*)d_in[1];
    const float* b       = (const float*)d_in[2];
    const int*   triples = (const int*)d_in[3];
    float*       out     = (float*)d_out;

    int n_nodes = in_sizes[0] / N_DIM;   // 100000
    int n_tr    = in_sizes[3] / 3;       // 200000

    static bool attr_set = false;
    if (!attr_set) {
        cudaFuncSetAttribute(gemm_kernel, cudaFuncAttributeMaxDynamicSharedMemorySize, SMEM_BYTES);
        attr_set = true;
    }

    prep_kernel<<<(128 * 512 + 255) / 256, 256>>>(W);
    gemm_kernel<<<(n_nodes + 127) / 128, 256, SMEM_BYTES>>>(emb, n_nodes);
    gather_kernel<<<(n_tr + 255) / 256, 256>>>(triples, b, out, n_tr);
}